// round 5
// baseline (speedup 1.0000x reference)
#include <cuda_runtime.h>
#include <math.h>

#define NPTS 16384
#define KNN 8
#define KSPLIT 8
#define KNN_TPB 128
#define KCHUNK 1024

// ---------------- scratch (static device globals; no allocation) ----------------
__device__ float g_pd[KSPLIT * NPTS * KNN];
__device__ int   g_pi[KSPLIT * NPTS * KNN];
__device__ int   g_idx[NPTS * KNN];
__device__ float g_P1[NPTS * 32];
__device__ float g_S1[NPTS * 32];
__device__ float g_x1[NPTS * 64];
__device__ float g_P2[NPTS * 64];
__device__ float g_S2[NPTS * 64];
__device__ float g_x2[NPTS * 128];

// Sorted top-8 insertion, static indices only (stays in registers).
__device__ __forceinline__ void insert8(float d, int jj, float bd[KNN], int bi[KNN]) {
#pragma unroll
  for (int s = KNN - 1; s >= 1; s--) {
    bool shift = (d < bd[s - 1]);
    bd[s] = shift ? bd[s - 1] : d;
    bi[s] = shift ? bi[s - 1] : jj;
    if (!shift) return;
  }
  bd[0] = d; bi[0] = jj;
}

// ---------------- kNN: candidate-split brute force ----------------
__global__ void knn_partial_kernel(const float* __restrict__ pos) {
  __shared__ float4 sc[KCHUNK];
  const int i = blockIdx.x * KNN_TPB + threadIdx.x;
  const float xi = pos[3 * i], yi = pos[3 * i + 1], zi = pos[3 * i + 2];
  const float sqi = fmaf(xi, xi, fmaf(yi, yi, zi * zi));
  float bd[KNN]; int bi[KNN];
#pragma unroll
  for (int s = 0; s < KNN; s++) { bd[s] = 3.0e38f; bi[s] = -1; }
  float worst = 3.0e38f;
  const int cbeg = blockIdx.y * (NPTS / KSPLIT);
  const int cend = cbeg + (NPTS / KSPLIT);
  for (int c0 = cbeg; c0 < cend; c0 += KCHUNK) {
    __syncthreads();
    for (int j = threadIdx.x; j < KCHUNK; j += KNN_TPB) {
      const int jj = c0 + j;
      const float x = pos[3 * jj], y = pos[3 * jj + 1], z = pos[3 * jj + 2];
      sc[j] = make_float4(x, y, z, fmaf(x, x, fmaf(y, y, z * z)));
    }
    __syncthreads();
#pragma unroll 4
    for (int j = 0; j < KCHUNK; j++) {
      const float4 p = sc[j];
      const float t = fmaf(xi, p.x, fmaf(yi, p.y, zi * p.z));
      const float d = fmaf(-2.0f, t, sqi + p.w);  // same formula as reference
      const int jj = c0 + j;
      if (d < worst && jj != i) {   // exclude self here (a split could hold all 8 NN)
        insert8(d, jj, bd, bi);
        worst = bd[KNN - 1];
      }
    }
  }
  const int base = (blockIdx.y * NPTS + i) * KNN;
#pragma unroll
  for (int s = 0; s < KNN; s++) { g_pd[base + s] = bd[s]; g_pi[base + s] = bi[s]; }
}

__global__ void knn_merge_kernel() {
  const int i = blockIdx.x * blockDim.x + threadIdx.x;
  float bd[KNN]; int bi[KNN];
#pragma unroll
  for (int s = 0; s < KNN; s++) { bd[s] = 3.0e38f; bi[s] = -1; }
  for (int sp = 0; sp < KSPLIT; sp++) {  // ascending split order -> tie stability
    const int base = (sp * NPTS + i) * KNN;
#pragma unroll
    for (int s = 0; s < KNN; s++) {
      const float d = g_pd[base + s];
      const int jj = g_pi[base + s];
      if (d < bd[KNN - 1]) insert8(d, jj, bd, bi);
    }
  }
#pragma unroll
  for (int s = 0; s < KNN; s++) g_idx[i * KNN + s] = bi[s];
}

// ---------------- layer-1 factoring: P1[j] = pos_j@(Wtop+Wbot)+b1a, S1[i] = pos_i@Wbot
__global__ void pre1_kernel(const float* __restrict__ pos,
                            const float* __restrict__ W1a,
                            const float* __restrict__ b1a) {
  __shared__ float w[6 * 32];
  __shared__ float b[32];
  if (threadIdx.x < 192) w[threadIdx.x] = W1a[threadIdx.x];
  if (threadIdx.x < 32) b[threadIdx.x] = b1a[threadIdx.x];
  __syncthreads();
  const int t = blockIdx.x * blockDim.x + threadIdx.x;
  const int i = t >> 5, c = t & 31;
  const float x = pos[3 * i], y = pos[3 * i + 1], z = pos[3 * i + 2];
  const float cb = fmaf(x, w[96 + c], fmaf(y, w[128 + c], z * w[160 + c]));
  const float pa = fmaf(x, w[c], fmaf(y, w[32 + c], fmaf(z, w[64 + c], b[c])));
  g_P1[t] = pa + cb;
  g_S1[t] = cb;
}

// ---------------- layer-2 factoring: P2[j] = x1_j@W2a[:64] + pos_j@W2a[64:67] + b2a,
//                  S2[i] = pos_i@W2a[64:67]
__global__ void pre2_kernel(const float* __restrict__ pos,
                            const float* __restrict__ W2a,
                            const float* __restrict__ b2a) {
  __shared__ float w[67 * 64];
  for (int q = threadIdx.x; q < 67 * 64; q += blockDim.x) w[q] = W2a[q];
  __syncthreads();
  const int t = blockIdx.x * blockDim.x + threadIdx.x;
  const int i = t >> 6, c = t & 63;
  float acc = b2a[c];
  const float* xr = &g_x1[i * 64];
#pragma unroll 8
  for (int k = 0; k < 64; k++) acc = fmaf(xr[k], w[k * 64 + c], acc);
  const float x = pos[3 * i], y = pos[3 * i + 1], z = pos[3 * i + 2];
  const float r = fmaf(x, w[64 * 64 + c], fmaf(y, w[65 * 64 + c], z * w[66 * 64 + c]));
  g_P2[t] = acc + r;
  g_S2[t] = r;
}

// ---------------- shared conv core: h = relu(P[j]-S[i]); out = relu(max_s(h@W2) + b2)
template <int HD, int OD, int PTS>
__device__ __forceinline__ void conv_impl(const float* __restrict__ P,
                                          const float* __restrict__ S,
                                          const float* __restrict__ W2,
                                          const float* __restrict__ b2,
                                          float* __restrict__ out) {
  constexpr int HSTR = PTS + 4;  // pad -> conflict-free transposed STS, aligned LDS.128
  constexpr int SSTR = HD + 4;
  constexpr int CHG = OD / 4;
  __shared__ float Hsm[HD * HSTR];
  __shared__ float Ssm[PTS * SSTR];
  __shared__ int Ism[PTS * KNN];
  const int t = threadIdx.x;
  const int pt_base = blockIdx.x * PTS;
  const int chg = t % CHG;
  const int ptg = t / CHG;
  {  // stage S (coalesced read, padded rows)
    const int lin = t * 8;  // PTS*HD == 2048 for both instantiations
    const int p = lin / HD, k = lin % HD;
    const float4 a = *(const float4*)&S[(pt_base + p) * HD + k];
    const float4 bq = *(const float4*)&S[(pt_base + p) * HD + k + 4];
    *(float4*)&Ssm[p * SSTR + k] = a;
    *(float4*)&Ssm[p * SSTR + k + 4] = bq;
  }
  for (int q = t; q < PTS * KNN; q += 256) Ism[q] = g_idx[pt_base * KNN + q];

  float4 acc0 = make_float4(-1e30f, -1e30f, -1e30f, -1e30f);
  float4 acc1 = acc0, acc2 = acc0, acc3 = acc0;

  const int fp = t % PTS;        // fill role: point
  const int fk = (t / PTS) * 8;  // fill role: k0

  for (int s = 0; s <= KNN; s++) {  // 8 NN + self
    __syncthreads();
    {
      const int j = (s < KNN) ? Ism[fp * KNN + s] : (pt_base + fp);
      const float4 a = *(const float4*)&P[j * HD + fk];
      const float4 bq = *(const float4*)&P[j * HD + fk + 4];
      const float4 sa = *(const float4*)&Ssm[fp * SSTR + fk];
      const float4 sb = *(const float4*)&Ssm[fp * SSTR + fk + 4];
      Hsm[(fk + 0) * HSTR + fp] = fmaxf(a.x - sa.x, 0.f);
      Hsm[(fk + 1) * HSTR + fp] = fmaxf(a.y - sa.y, 0.f);
      Hsm[(fk + 2) * HSTR + fp] = fmaxf(a.z - sa.z, 0.f);
      Hsm[(fk + 3) * HSTR + fp] = fmaxf(a.w - sa.w, 0.f);
      Hsm[(fk + 4) * HSTR + fp] = fmaxf(bq.x - sb.x, 0.f);
      Hsm[(fk + 5) * HSTR + fp] = fmaxf(bq.y - sb.y, 0.f);
      Hsm[(fk + 6) * HSTR + fp] = fmaxf(bq.z - sb.z, 0.f);
      Hsm[(fk + 7) * HSTR + fp] = fmaxf(bq.w - sb.w, 0.f);
    }
    __syncthreads();
    float4 o0 = make_float4(0.f, 0.f, 0.f, 0.f), o1 = o0, o2 = o0, o3 = o0;
#pragma unroll 8
    for (int k = 0; k < HD; k++) {
      const float4 h = *(const float4*)&Hsm[k * HSTR + ptg * 4];  // broadcast
      const float4 w = __ldg((const float4*)&W2[k * OD + chg * 4]);  // L1-resident
      o0.x = fmaf(h.x, w.x, o0.x); o0.y = fmaf(h.x, w.y, o0.y);
      o0.z = fmaf(h.x, w.z, o0.z); o0.w = fmaf(h.x, w.w, o0.w);
      o1.x = fmaf(h.y, w.x, o1.x); o1.y = fmaf(h.y, w.y, o1.y);
      o1.z = fmaf(h.y, w.z, o1.z); o1.w = fmaf(h.y, w.w, o1.w);
      o2.x = fmaf(h.z, w.x, o2.x); o2.y = fmaf(h.z, w.y, o2.y);
      o2.z = fmaf(h.z, w.z, o2.z); o2.w = fmaf(h.z, w.w, o2.w);
      o3.x = fmaf(h.w, w.x, o3.x); o3.y = fmaf(h.w, w.y, o3.y);
      o3.z = fmaf(h.w, w.z, o3.z); o3.w = fmaf(h.w, w.w, o3.w);
    }
    acc0.x = fmaxf(acc0.x, o0.x); acc0.y = fmaxf(acc0.y, o0.y);
    acc0.z = fmaxf(acc0.z, o0.z); acc0.w = fmaxf(acc0.w, o0.w);
    acc1.x = fmaxf(acc1.x, o1.x); acc1.y = fmaxf(acc1.y, o1.y);
    acc1.z = fmaxf(acc1.z, o1.z); acc1.w = fmaxf(acc1.w, o1.w);
    acc2.x = fmaxf(acc2.x, o2.x); acc2.y = fmaxf(acc2.y, o2.y);
    acc2.z = fmaxf(acc2.z, o2.z); acc2.w = fmaxf(acc2.w, o2.w);
    acc3.x = fmaxf(acc3.x, o3.x); acc3.y = fmaxf(acc3.y, o3.y);
    acc3.z = fmaxf(acc3.z, o3.z); acc3.w = fmaxf(acc3.w, o3.w);
  }
  const float4 bb = __ldg((const float4*)&b2[chg * 4]);
  const int c0 = chg * 4;
  const int i0 = pt_base + ptg * 4;
  float4 r;
  r.x = fmaxf(acc0.x + bb.x, 0.f); r.y = fmaxf(acc0.y + bb.y, 0.f);
  r.z = fmaxf(acc0.z + bb.z, 0.f); r.w = fmaxf(acc0.w + bb.w, 0.f);
  *(float4*)&out[(i0 + 0) * OD + c0] = r;
  r.x = fmaxf(acc1.x + bb.x, 0.f); r.y = fmaxf(acc1.y + bb.y, 0.f);
  r.z = fmaxf(acc1.z + bb.z, 0.f); r.w = fmaxf(acc1.w + bb.w, 0.f);
  *(float4*)&out[(i0 + 1) * OD + c0] = r;
  r.x = fmaxf(acc2.x + bb.x, 0.f); r.y = fmaxf(acc2.y + bb.y, 0.f);
  r.z = fmaxf(acc2.z + bb.z, 0.f); r.w = fmaxf(acc2.w + bb.w, 0.f);
  *(float4*)&out[(i0 + 2) * OD + c0] = r;
  r.x = fmaxf(acc3.x + bb.x, 0.f); r.y = fmaxf(acc3.y + bb.y, 0.f);
  r.z = fmaxf(acc3.z + bb.z, 0.f); r.w = fmaxf(acc3.w + bb.w, 0.f);
  *(float4*)&out[(i0 + 3) * OD + c0] = r;
}

__global__ void conv1_kernel(const float* __restrict__ W2, const float* __restrict__ b2) {
  conv_impl<32, 64, 64>(g_P1, g_S1, W2, b2, g_x1);
}
__global__ void conv2_kernel(const float* __restrict__ W2, const float* __restrict__ b2) {
  conv_impl<64, 128, 32>(g_P2, g_S2, W2, b2, g_x2);
}

// ---------------- classifier + log_softmax ----------------
#define CLS_WARPS 2
__global__ void classifier_kernel(const float* __restrict__ Wc,
                                  const float* __restrict__ bc,
                                  float* __restrict__ out) {
  __shared__ float xs[CLS_WARPS * 32 * 132];
  __shared__ float wsm[128 * 5];
  __shared__ float bsm[5];
  const int t = threadIdx.x;
  for (int q = t; q < 640; q += 64) wsm[q] = Wc[q];
  if (t < 5) bsm[t] = bc[t];
  const int w = t >> 5, l = t & 31;
  const int base = (blockIdx.x * CLS_WARPS + w) * 32;
  float* xw = &xs[w * 32 * 132];
  for (int r = 0; r < 32; r++) {
    *(float4*)&xw[r * 132 + l * 4] = *(const float4*)&g_x2[(base + r) * 128 + l * 4];
  }
  __syncthreads();
  float a0 = bsm[0], a1 = bsm[1], a2 = bsm[2], a3 = bsm[3], a4 = bsm[4];
  const float* xr = &xw[l * 132];
#pragma unroll 4
  for (int k = 0; k < 128; k++) {
    const float xv = xr[k];
    a0 = fmaf(xv, wsm[k * 5 + 0], a0);
    a1 = fmaf(xv, wsm[k * 5 + 1], a1);
    a2 = fmaf(xv, wsm[k * 5 + 2], a2);
    a3 = fmaf(xv, wsm[k * 5 + 3], a3);
    a4 = fmaf(xv, wsm[k * 5 + 4], a4);
  }
  const float m = fmaxf(fmaxf(fmaxf(a0, a1), fmaxf(a2, a3)), a4);
  const float sum = expf(a0 - m) + expf(a1 - m) + expf(a2 - m) +
                    expf(a3 - m) + expf(a4 - m);
  const float lse = m + logf(sum);
  const int o = (base + l) * 5;
  out[o + 0] = a0 - lse;
  out[o + 1] = a1 - lse;
  out[o + 2] = a2 - lse;
  out[o + 3] = a3 - lse;
  out[o + 4] = a4 - lse;
}

// ---------------- launch ----------------
extern "C" void kernel_launch(void* const* d_in, const int* in_sizes, int n_in,
                              void* d_out, int out_size) {
  const float* pos = (const float*)d_in[0];
  const float* W1a = (const float*)d_in[1];
  const float* b1a = (const float*)d_in[2];
  const float* W1b = (const float*)d_in[3];
  const float* b1b = (const float*)d_in[4];
  const float* W2a = (const float*)d_in[5];
  const float* b2a = (const float*)d_in[6];
  const float* W2b = (const float*)d_in[7];
  const float* b2b = (const float*)d_in[8];
  const float* Wc  = (const float*)d_in[9];
  const float* bc  = (const float*)d_in[10];
  float* out = (float*)d_out;

  knn_partial_kernel<<<dim3(NPTS / KNN_TPB, KSPLIT), KNN_TPB>>>(pos);
  knn_merge_kernel<<<NPTS / 256, 256>>>();
  pre1_kernel<<<(NPTS * 32) / 256, 256>>>(pos, W1a, b1a);
  conv1_kernel<<<NPTS / 64, 256>>>(W1b, b1b);
  pre2_kernel<<<(NPTS * 64) / 256, 256>>>(pos, W2a, b2a);
  conv2_kernel<<<NPTS / 32, 256>>>(W2b, b2b);
  classifier_kernel<<<NPTS / (32 * CLS_WARPS), 64>>>(Wc, bc, out);
}

// round 6
// speedup vs baseline: 1.2242x; 1.2242x over previous
#include <cuda_runtime.h>
#include <math.h>

#define NPTS 16384
#define KNN 8
#define KSPLIT 16
#define KNN_TPB 128
#define QPT 4
#define KCHUNK 1024   // == NPTS/KSPLIT -> single chunk per block

// ---------------- scratch (static device globals; no allocation) ----------------
__device__ float g_pd[KSPLIT * NPTS * KNN];
__device__ int   g_pi[KSPLIT * NPTS * KNN];
__device__ int   g_idx[NPTS * KNN];
__device__ float g_P1[NPTS * 32];
__device__ float g_S1[NPTS * 32];
__device__ float g_x1[NPTS * 64];
__device__ float g_P2[NPTS * 64];
__device__ float g_S2[NPTS * 64];
__device__ float g_x2[NPTS * 128];

// Sorted top-8 insertion, static indices only (stays in registers).
__device__ __forceinline__ void insert8(float d, int jj, float bd[KNN], int bi[KNN]) {
#pragma unroll
  for (int s = KNN - 1; s >= 1; s--) {
    bool shift = (d < bd[s - 1]);
    bd[s] = shift ? bd[s - 1] : d;
    bi[s] = shift ? bi[s - 1] : jj;
    if (!shift) return;
  }
  bd[0] = d; bi[0] = jj;
}

// ---------------- kNN: candidate-split brute force, 4 queries per thread ----------
__global__ void __launch_bounds__(KNN_TPB) knn_partial_kernel(const float* __restrict__ pos) {
  __shared__ __align__(16) float4 sc[KCHUNK];
  const int tid = threadIdx.x;
  const int qbase = (blockIdx.x * KNN_TPB + tid) * QPT;

  float qx[QPT], qy[QPT], qz[QPT], qs[QPT];
#pragma unroll
  for (int q = 0; q < QPT; q++) {
    const float x = pos[3 * (qbase + q)];
    const float y = pos[3 * (qbase + q) + 1];
    const float z = pos[3 * (qbase + q) + 2];
    qx[q] = x; qy[q] = y; qz[q] = z;
    qs[q] = fmaf(x, x, fmaf(y, y, z * z));
  }

  float bd[QPT][KNN]; int bi[QPT][KNN]; float worst[QPT];
#pragma unroll
  for (int q = 0; q < QPT; q++) {
#pragma unroll
    for (int s = 0; s < KNN; s++) { bd[q][s] = 3.0e38f; bi[q][s] = -1; }
    worst[q] = 3.0e38f;
  }

  const int c0 = blockIdx.y * KCHUNK;
  // stage candidates (one chunk == the whole split)
  for (int j = tid; j < KCHUNK; j += KNN_TPB) {
    const int jj = c0 + j;
    const float x = pos[3 * jj], y = pos[3 * jj + 1], z = pos[3 * jj + 2];
    sc[j] = make_float4(x, y, z, fmaf(x, x, fmaf(y, y, z * z)));
  }
  __syncthreads();

#pragma unroll 4
  for (int j = 0; j < KCHUNK; j++) {
    const float4 p = sc[j];
    const int jj = c0 + j;
#pragma unroll
    for (int q = 0; q < QPT; q++) {
      const float t = fmaf(qx[q], p.x, fmaf(qy[q], p.y, qz[q] * p.z));
      const float d = fmaf(-2.0f, t, qs[q] + p.w);  // same formula as reference
      if (d < worst[q] && jj != qbase + q) {
        insert8(d, jj, bd[q], bi[q]);
        worst[q] = bd[q][KNN - 1];
      }
    }
  }

#pragma unroll
  for (int q = 0; q < QPT; q++) {
    const int base = (blockIdx.y * NPTS + qbase + q) * KNN;
#pragma unroll
    for (int s = 0; s < KNN; s++) { g_pd[base + s] = bd[q][s]; g_pi[base + s] = bi[q][s]; }
  }
}

__global__ void knn_merge_kernel() {
  const int i = blockIdx.x * blockDim.x + threadIdx.x;
  float bd[KNN]; int bi[KNN];
#pragma unroll
  for (int s = 0; s < KNN; s++) { bd[s] = 3.0e38f; bi[s] = -1; }
  for (int sp = 0; sp < KSPLIT; sp++) {  // ascending split order -> tie stability
    const int base = (sp * NPTS + i) * KNN;
    const float4 d0 = *(const float4*)&g_pd[base];
    const float4 d1 = *(const float4*)&g_pd[base + 4];
    const int4 i0 = *(const int4*)&g_pi[base];
    const int4 i1 = *(const int4*)&g_pi[base + 4];
    float dv[KNN] = {d0.x, d0.y, d0.z, d0.w, d1.x, d1.y, d1.z, d1.w};
    int iv[KNN] = {i0.x, i0.y, i0.z, i0.w, i1.x, i1.y, i1.z, i1.w};
#pragma unroll
    for (int s = 0; s < KNN; s++) {
      if (dv[s] < bd[KNN - 1]) insert8(dv[s], iv[s], bd, bi);
    }
  }
#pragma unroll
  for (int s = 0; s < KNN; s++) g_idx[i * KNN + s] = bi[s];
}

// ---------------- layer-1 factoring: P1[j] = pos_j@(Wtop+Wbot)+b1a, S1[i] = pos_i@Wbot
__global__ void pre1_kernel(const float* __restrict__ pos,
                            const float* __restrict__ W1a,
                            const float* __restrict__ b1a) {
  __shared__ float w[6 * 32];
  __shared__ float b[32];
  if (threadIdx.x < 192) w[threadIdx.x] = W1a[threadIdx.x];
  if (threadIdx.x < 32) b[threadIdx.x] = b1a[threadIdx.x];
  __syncthreads();
  const int t = blockIdx.x * blockDim.x + threadIdx.x;
  const int i = t >> 5, c = t & 31;
  const float x = pos[3 * i], y = pos[3 * i + 1], z = pos[3 * i + 2];
  const float cb = fmaf(x, w[96 + c], fmaf(y, w[128 + c], z * w[160 + c]));
  const float pa = fmaf(x, w[c], fmaf(y, w[32 + c], fmaf(z, w[64 + c], b[c])));
  g_P1[t] = pa + cb;
  g_S1[t] = cb;
}

// ---------------- layer-2 factoring: P2[j] = x1_j@W2a[:64] + pos_j@W2a[64:67] + b2a,
//                  S2[i] = pos_i@W2a[64:67]   (weights via L1-resident __ldg)
__global__ void pre2_kernel(const float* __restrict__ pos,
                            const float* __restrict__ W2a,
                            const float* __restrict__ b2a) {
  const int t = blockIdx.x * blockDim.x + threadIdx.x;
  const int i = t >> 6, c = t & 63;
  float acc = __ldg(&b2a[c]);
  const float* xr = &g_x1[i * 64];
#pragma unroll 8
  for (int k = 0; k < 64; k++) acc = fmaf(xr[k], __ldg(&W2a[k * 64 + c]), acc);
  const float x = pos[3 * i], y = pos[3 * i + 1], z = pos[3 * i + 2];
  const float r = fmaf(x, __ldg(&W2a[64 * 64 + c]),
                  fmaf(y, __ldg(&W2a[65 * 64 + c]), z * __ldg(&W2a[66 * 64 + c])));
  g_P2[t] = acc + r;
  g_S2[t] = r;
}

// ---------------- shared conv core: h = relu(P[j]-S[i]); out = relu(max_s(h@W2) + b2)
template <int HD, int OD, int PTS, int NT>
__device__ __forceinline__ void conv_impl(const float* __restrict__ P,
                                          const float* __restrict__ S,
                                          const float* __restrict__ W2,
                                          const float* __restrict__ b2,
                                          float* __restrict__ out) {
  constexpr int HSTR = PTS + 4;  // pad -> conflict-free transposed STS, aligned LDS.128
  constexpr int SSTR = HD + 4;
  constexpr int CHG = OD / 4;
  __shared__ __align__(16) float Hsm[HD * HSTR];
  __shared__ __align__(16) float Ssm[PTS * SSTR];
  __shared__ int Ism[PTS * KNN];
  const int t = threadIdx.x;
  const int pt_base = blockIdx.x * PTS;
  const int chg = t % CHG;
  const int ptg = t / CHG;
  {  // stage S (coalesced read, padded rows); PTS*HD == NT*8 for both instantiations
    const int lin = t * 8;
    const int p = lin / HD, k = lin % HD;
    const float4 a = *(const float4*)&S[(pt_base + p) * HD + k];
    const float4 bq = *(const float4*)&S[(pt_base + p) * HD + k + 4];
    *(float4*)&Ssm[p * SSTR + k] = a;
    *(float4*)&Ssm[p * SSTR + k + 4] = bq;
  }
  for (int q = t; q < PTS * KNN; q += NT) Ism[q] = g_idx[pt_base * KNN + q];

  float4 acc0 = make_float4(-1e30f, -1e30f, -1e30f, -1e30f);
  float4 acc1 = acc0, acc2 = acc0, acc3 = acc0;

  const int fp = t % PTS;        // fill role: point
  const int fk = (t / PTS) * 8;  // fill role: k0

  for (int s = 0; s <= KNN; s++) {  // 8 NN + self
    __syncthreads();
    {
      const int j = (s < KNN) ? Ism[fp * KNN + s] : (pt_base + fp);
      const float4 a = *(const float4*)&P[j * HD + fk];
      const float4 bq = *(const float4*)&P[j * HD + fk + 4];
      const float4 sa = *(const float4*)&Ssm[fp * SSTR + fk];
      const float4 sb = *(const float4*)&Ssm[fp * SSTR + fk + 4];
      Hsm[(fk + 0) * HSTR + fp] = fmaxf(a.x - sa.x, 0.f);
      Hsm[(fk + 1) * HSTR + fp] = fmaxf(a.y - sa.y, 0.f);
      Hsm[(fk + 2) * HSTR + fp] = fmaxf(a.z - sa.z, 0.f);
      Hsm[(fk + 3) * HSTR + fp] = fmaxf(a.w - sa.w, 0.f);
      Hsm[(fk + 4) * HSTR + fp] = fmaxf(bq.x - sb.x, 0.f);
      Hsm[(fk + 5) * HSTR + fp] = fmaxf(bq.y - sb.y, 0.f);
      Hsm[(fk + 6) * HSTR + fp] = fmaxf(bq.z - sb.z, 0.f);
      Hsm[(fk + 7) * HSTR + fp] = fmaxf(bq.w - sb.w, 0.f);
    }
    __syncthreads();
    float4 o0 = make_float4(0.f, 0.f, 0.f, 0.f), o1 = o0, o2 = o0, o3 = o0;
#pragma unroll 8
    for (int k = 0; k < HD; k++) {
      const float4 h = *(const float4*)&Hsm[k * HSTR + ptg * 4];  // broadcast
      const float4 w = __ldg((const float4*)&W2[k * OD + chg * 4]);  // L1-resident
      o0.x = fmaf(h.x, w.x, o0.x); o0.y = fmaf(h.x, w.y, o0.y);
      o0.z = fmaf(h.x, w.z, o0.z); o0.w = fmaf(h.x, w.w, o0.w);
      o1.x = fmaf(h.y, w.x, o1.x); o1.y = fmaf(h.y, w.y, o1.y);
      o1.z = fmaf(h.y, w.z, o1.z); o1.w = fmaf(h.y, w.w, o1.w);
      o2.x = fmaf(h.z, w.x, o2.x); o2.y = fmaf(h.z, w.y, o2.y);
      o2.z = fmaf(h.z, w.z, o2.z); o2.w = fmaf(h.z, w.w, o2.w);
      o3.x = fmaf(h.w, w.x, o3.x); o3.y = fmaf(h.w, w.y, o3.y);
      o3.z = fmaf(h.w, w.z, o3.z); o3.w = fmaf(h.w, w.w, o3.w);
    }
    acc0.x = fmaxf(acc0.x, o0.x); acc0.y = fmaxf(acc0.y, o0.y);
    acc0.z = fmaxf(acc0.z, o0.z); acc0.w = fmaxf(acc0.w, o0.w);
    acc1.x = fmaxf(acc1.x, o1.x); acc1.y = fmaxf(acc1.y, o1.y);
    acc1.z = fmaxf(acc1.z, o1.z); acc1.w = fmaxf(acc1.w, o1.w);
    acc2.x = fmaxf(acc2.x, o2.x); acc2.y = fmaxf(acc2.y, o2.y);
    acc2.z = fmaxf(acc2.z, o2.z); acc2.w = fmaxf(acc2.w, o2.w);
    acc3.x = fmaxf(acc3.x, o3.x); acc3.y = fmaxf(acc3.y, o3.y);
    acc3.z = fmaxf(acc3.z, o3.z); acc3.w = fmaxf(acc3.w, o3.w);
  }
  const float4 bb = __ldg((const float4*)&b2[chg * 4]);
  const int c0 = chg * 4;
  const int i0 = pt_base + ptg * 4;
  float4 r;
  r.x = fmaxf(acc0.x + bb.x, 0.f); r.y = fmaxf(acc0.y + bb.y, 0.f);
  r.z = fmaxf(acc0.z + bb.z, 0.f); r.w = fmaxf(acc0.w + bb.w, 0.f);
  *(float4*)&out[(i0 + 0) * OD + c0] = r;
  r.x = fmaxf(acc1.x + bb.x, 0.f); r.y = fmaxf(acc1.y + bb.y, 0.f);
  r.z = fmaxf(acc1.z + bb.z, 0.f); r.w = fmaxf(acc1.w + bb.w, 0.f);
  *(float4*)&out[(i0 + 1) * OD + c0] = r;
  r.x = fmaxf(acc2.x + bb.x, 0.f); r.y = fmaxf(acc2.y + bb.y, 0.f);
  r.z = fmaxf(acc2.z + bb.z, 0.f); r.w = fmaxf(acc2.w + bb.w, 0.f);
  *(float4*)&out[(i0 + 2) * OD + c0] = r;
  r.x = fmaxf(acc3.x + bb.x, 0.f); r.y = fmaxf(acc3.y + bb.y, 0.f);
  r.z = fmaxf(acc3.z + bb.z, 0.f); r.w = fmaxf(acc3.w + bb.w, 0.f);
  *(float4*)&out[(i0 + 3) * OD + c0] = r;
}

// conv1: PTS=32 with 128 threads -> 512 CTAs (was 256) to fix grid-limited occupancy
__global__ void conv1_kernel(const float* __restrict__ W2, const float* __restrict__ b2) {
  conv_impl<32, 64, 32, 128>(g_P1, g_S1, W2, b2, g_x1);
}
__global__ void conv2_kernel(const float* __restrict__ W2, const float* __restrict__ b2) {
  conv_impl<64, 128, 32, 256>(g_P2, g_S2, W2, b2, g_x2);
}

// ---------------- classifier + log_softmax ----------------
#define CLS_WARPS 2
__global__ void classifier_kernel(const float* __restrict__ Wc,
                                  const float* __restrict__ bc,
                                  float* __restrict__ out) {
  __shared__ __align__(16) float xs[CLS_WARPS * 32 * 132];
  __shared__ float wsm[128 * 5];
  __shared__ float bsm[5];
  const int t = threadIdx.x;
  for (int q = t; q < 640; q += 64) wsm[q] = Wc[q];
  if (t < 5) bsm[t] = bc[t];
  const int w = t >> 5, l = t & 31;
  const int base = (blockIdx.x * CLS_WARPS + w) * 32;
  float* xw = &xs[w * 32 * 132];
  for (int r = 0; r < 32; r++) {
    *(float4*)&xw[r * 132 + l * 4] = *(const float4*)&g_x2[(base + r) * 128 + l * 4];
  }
  __syncthreads();
  float a0 = bsm[0], a1 = bsm[1], a2 = bsm[2], a3 = bsm[3], a4 = bsm[4];
  const float* xr = &xw[l * 132];
#pragma unroll 4
  for (int k = 0; k < 128; k++) {
    const float xv = xr[k];
    a0 = fmaf(xv, wsm[k * 5 + 0], a0);
    a1 = fmaf(xv, wsm[k * 5 + 1], a1);
    a2 = fmaf(xv, wsm[k * 5 + 2], a2);
    a3 = fmaf(xv, wsm[k * 5 + 3], a3);
    a4 = fmaf(xv, wsm[k * 5 + 4], a4);
  }
  const float m = fmaxf(fmaxf(fmaxf(a0, a1), fmaxf(a2, a3)), a4);
  const float sum = expf(a0 - m) + expf(a1 - m) + expf(a2 - m) +
                    expf(a3 - m) + expf(a4 - m);
  const float lse = m + logf(sum);
  const int o = (base + l) * 5;
  out[o + 0] = a0 - lse;
  out[o + 1] = a1 - lse;
  out[o + 2] = a2 - lse;
  out[o + 3] = a3 - lse;
  out[o + 4] = a4 - lse;
}

// ---------------- launch ----------------
extern "C" void kernel_launch(void* const* d_in, const int* in_sizes, int n_in,
                              void* d_out, int out_size) {
  const float* pos = (const float*)d_in[0];
  const float* W1a = (const float*)d_in[1];
  const float* b1a = (const float*)d_in[2];
  const float* W1b = (const float*)d_in[3];
  const float* b1b = (const float*)d_in[4];
  const float* W2a = (const float*)d_in[5];
  const float* b2a = (const float*)d_in[6];
  const float* W2b = (const float*)d_in[7];
  const float* b2b = (const float*)d_in[8];
  const float* Wc  = (const float*)d_in[9];
  const float* bc  = (const float*)d_in[10];
  float* out = (float*)d_out;

  knn_partial_kernel<<<dim3(NPTS / (KNN_TPB * QPT), KSPLIT), KNN_TPB>>>(pos);
  knn_merge_kernel<<<NPTS / 256, 256>>>();
  pre1_kernel<<<(NPTS * 32) / 256, 256>>>(pos, W1a, b1a);
  conv1_kernel<<<NPTS / 32, 128>>>(W1b, b1b);
  pre2_kernel<<<(NPTS * 64) / 256, 256>>>(pos, W2a, b2a);
  conv2_kernel<<<NPTS / 32, 256>>>(W2b, b2b);
  classifier_kernel<<<NPTS / (32 * CLS_WARPS), 64>>>(Wc, bc, out);
}